// round 14
// baseline (speedup 1.0000x reference)
#include <cuda_runtime.h>
#include <cstdint>

// ---------------- problem constants ----------------
#define BB 16
#define TT 12
#define FF 32
#define H1 48
#define W1 48
#define C1 3
#define HO1 47
#define WO1 46
#define H2 47
#define W2 46
#define HO2 46
#define WO2 44
#define FLAT 194304
#define NCHUNK 256
#define CHUNK 759   // 256*759 = 194304 exactly

#define H1SLICE (BB * HO1 * WO1 * FF)
#define H2SLICE (BB * HO2 * WO2 * FF)
#define APAD 40
#define STAGE_FLOATS 10240              // As 5120 + Bs 5120
#define SMEM_BYTES (2 * STAGE_FLOATS * 4)

// ---------------- device scratch ----------------
__device__ float g_h1[(long)TT * BB * HO1 * WO1 * FF];
__device__ float g_h2[(long)TT * BB * HO2 * WO2 * FF];
__device__ float g_c[2 * BB * HO1 * WO1 * FF];
__device__ float g_hzero[BB * HO1 * WO1 * FF];          // zero-init, never written
__device__ float g_part[NCHUNK * BB * 10];
__device__ float g_xr[BB * TT * H1 * W1 * C1];          // tf32-rounded input
// B chunk tiles in FRAGMENT layout: [chunk][wn(2)][kb(4)][lane(32)][nt*2+e (16)]
__device__ float g_B1[7 * 4096];
__device__ float g_B2[12 * 4096];

__device__ __forceinline__ float hsig(float x) {
    return fminf(fmaxf(fmaf(0.2f, x, 0.5f), 0.0f), 1.0f);
}
__device__ __forceinline__ float tf32r(float x) {
    uint32_t r;
    asm("cvt.rna.tf32.f32 %0, %1;" : "=r"(r) : "f"(x));
    return __uint_as_float(r);
}
// m16n8k8 tf32 MMA, D += A*B
__device__ __forceinline__ void mma_tf32(float* d, const uint32_t* a, uint32_t b0, uint32_t b1) {
    asm volatile(
        "mma.sync.aligned.m16n8k8.row.col.f32.tf32.tf32.f32 "
        "{%0,%1,%2,%3}, {%4,%5,%6,%7}, {%8,%9}, {%0,%1,%2,%3};"
        : "+f"(d[0]), "+f"(d[1]), "+f"(d[2]), "+f"(d[3])
        : "r"(a[0]), "r"(a[1]), "r"(a[2]), "r"(a[3]), "r"(b0), "r"(b1));
}

// Build B chunk tiles in fragment layout (tf32) + pre-round x.
__global__ void prep_kernel(const float* __restrict__ W1p, const float* __restrict__ U1p,
                            const float* __restrict__ W2p, const float* __restrict__ U2p,
                            const float* __restrict__ x,
                            float* __restrict__ B1, float* __restrict__ B2,
                            float* __restrict__ xr)
{
    int idx = blockIdx.x * blockDim.x + threadIdx.x;
    const int t1 = 7 * 4096, t2 = t1 + 12 * 4096;
    const int nx = BB * TT * H1 * W1 * C1;
    if (idx < t2) {
        int isL1 = idx < t1;
        int local = isL1 ? idx : idx - t1;
        int c = local >> 12, q = local & 4095;
        int wn = q >> 11;
        int kb = (q >> 9) & 3;
        int lane = (q >> 4) & 31;
        int nt = (q >> 1) & 7;
        int e = q & 1;
        int n = wn * 64 + nt * 8 + (lane >> 2);
        int k = kb * 8 + (lane & 3) + 4 * e;
        int col = (n & 3) * 32 + (n >> 2);
        float v;
        if (isL1) {
            if (c == 0) v = (k < 18) ? W1p[k * 128 + col] : 0.0f;
            else        v = U1p[((c - 1) * 32 + k) * 128 + col];
            B1[local] = tf32r(v);
        } else {
            v = (c < 6) ? W2p[(c * 32 + k) * 128 + col]
                        : U2p[((c - 6) * 32 + k) * 128 + col];
            B2[local] = tf32r(v);
        }
    } else if (idx < t2 + nx) {
        int i = idx - t2;
        xr[i] = tf32r(x[i]);
    }
}

// interleave two float4 (k 0..3 and k 4..7) into fragment order
__device__ __forceinline__ void interleave_sts(float* dst, float4 lo, float4 hi) {
    float4 p0 = make_float4(lo.x, hi.x, lo.y, hi.y);
    float4 p1 = make_float4(lo.z, hi.z, lo.w, hi.w);
    *(float4*)(dst)     = p0;
    *(float4*)(dst + 4) = p1;
}

// Fused step F(t): layer1 step t + layer2 step t-1, tf32 mma.sync implicit GEMM.
// Register prefetch + 2-stage smem double buffer, ONE __syncthreads per chunk.
// Grid (3,6,32): z = layer*16+batch; 256 threads = 8 warps (wm=warp&3, wn=warp>>2).
__global__ void __launch_bounds__(256, 2) fused_step_kernel(
    int t,
    const float* __restrict__ xr,
    float* __restrict__ h1, float* __restrict__ h2,
    const float* __restrict__ hz,
    float* __restrict__ cb1, float* __restrict__ cb2,
    const float* __restrict__ gB1, const float* __restrict__ gB2,
    const float* __restrict__ b1, const float* __restrict__ b2)
{
    extern __shared__ float sm[];   // [2][As 128*APAD | Bs 256*20]

    const int tid = threadIdx.x;
    const int lane = tid & 31;
    const int warp = tid >> 5;
    const int g = lane >> 2, tig = lane & 3;
    const int wm = warp & 3, wn = warp >> 2;
    const int z = blockIdx.z;
    const int layer = z >> 4, b = z & 15;
    const int y0 = blockIdx.y * 8, x0 = blockIdx.x * 16;

    if (layer == 0 && t >= TT) return;
    if (layer == 1 && t == 0) return;
    const int s = layer ? (t - 1) : t;

    const int Ho = layer ? HO2 : HO1;
    const int Wo = layer ? WO2 : WO1;
    const int hb = Ho * Wo * 32;
    const long slice = layer ? (long)H2SLICE : (long)H1SLICE;
    const float* gB = layer ? gB2 : gB1;
    const float* bias = layer ? b2 : b1;
    float* cbuf = layer ? cb2 : cb1;
    float* hseq = layer ? h2 : h1;
    float* hout = hseq + s * slice;
    const int have_h = (s != 0);
    const float* hprev = (have_h ? (hseq + (s - 1) * slice) : hz) + b * hb;
    const float* xsrc2 = h1 + (long)s * H1SLICE + b * (HO1 * WO1 * 32);

    const int nch = layer ? (have_h ? 12 : 6) : (have_h ? 7 : 1);

    float acc[2][8][4];
#pragma unroll
    for (int mt = 0; mt < 2; mt++)
#pragma unroll
        for (int nt = 0; nt < 8; nt++)
#pragma unroll
            for (int j = 0; j < 4; j++) acc[mt][nt][j] = 0.0f;

    // staging indices
    const int sm_m = tid >> 1, sm_kh = tid & 1;   // A: row m, k-half
    const int sm_py = sm_m >> 4, sm_px = sm_m & 15;

    float4 rA0, rA1, rA2, rA3;   // A prefetch regs
    float4 rB0, rB1, rB2, rB3;   // B prefetch regs (fragment row)

    auto ldgB = [&](int c) {
        const float4* sp = (const float4*)(gB + (c << 12) + tid * 16);
        rB0 = sp[0]; rB1 = sp[1]; rB2 = sp[2]; rB3 = sp[3];
    };
    auto ldgA = [&](int c) {
        if (layer == 0 && c == 0) {
            const float* xb = xr + (long)(b * TT + s) * (48 * 48 * 3);
            float tmp[16];
#pragma unroll
            for (int i = 0; i < 16; i++) {
                int k = sm_kh * 16 + i;
                float v = 0.0f;
                if (k < 18) {
                    int tap = k / 3, ci = k - tap * 3;
                    int dy = tap / 3, dx = tap - dy * 3;
                    int gy = y0 + sm_py + dy, gx = x0 + sm_px + dx;
                    if (gy < 48 && gx < 48) v = xb[(gy * 48 + gx) * 3 + ci];
                }
                tmp[i] = v;
            }
            rA0 = make_float4(tmp[0], tmp[1], tmp[2], tmp[3]);
            rA1 = make_float4(tmp[4], tmp[5], tmp[6], tmp[7]);
            rA2 = make_float4(tmp[8], tmp[9], tmp[10], tmp[11]);
            rA3 = make_float4(tmp[12], tmp[13], tmp[14], tmp[15]);
        } else {
            int cc, isH;
            if (layer == 0) { cc = c - 1; isH = 1; }
            else { isH = (c >= 6); cc = isH ? (c - 6) : c; }
            int dy = cc / 3, dx = cc - dy * 3;
            const float* src; int Hs, Ws, gx;
            int gy = y0 + sm_py + dy;
            if (isH) { src = hprev; Hs = Ho; Ws = Wo; gx = x0 + sm_px + dx - 1; }
            else     { src = xsrc2; Hs = H2; Ws = W2; gx = x0 + sm_px + dx; }
            bool ok = ((unsigned)gy < (unsigned)Hs) && ((unsigned)gx < (unsigned)Ws);
            if (ok) {
                const float4* sp = (const float4*)(src + (gy * Ws + gx) * 32 + sm_kh * 16);
                rA0 = sp[0]; rA1 = sp[1]; rA2 = sp[2]; rA3 = sp[3];
            } else {
                rA0 = rA1 = rA2 = rA3 = make_float4(0.f, 0.f, 0.f, 0.f);
            }
        }
    };

    ldgA(0);
    ldgB(0);

    for (int c = 0; c < nch; c++) {
        float* stage = sm + (c & 1) * STAGE_FLOATS;
        float* As = stage;
        float* Bs = stage + 128 * APAD;

        // ---- STS prefetched chunk into this stage ----
        {
            float* dp = Bs + tid * 20;
            *(float4*)(dp)      = rB0;
            *(float4*)(dp + 4)  = rB1;
            *(float4*)(dp + 8)  = rB2;
            *(float4*)(dp + 12) = rB3;
            float* Ad = As + sm_m * APAD + sm_kh * 16;
            interleave_sts(Ad, rA0, rA1);
            interleave_sts(Ad + 8, rA2, rA3);
        }
        __syncthreads();   // single barrier per chunk (double buffer makes tail sync unneeded)

        // ---- issue next chunk's LDGs (latency hidden by MMA phase) ----
        if (c + 1 < nch) { ldgA(c + 1); ldgB(c + 1); }

        // ---- MMA phase: 4 k8-blocks ----
        const float* Arow = As + (wm * 32 + g) * APAD;
        const float* Bbase = Bs + (wn * 4 * 32 + lane) * 20;
#pragma unroll
        for (int kb = 0; kb < 4; kb++) {
            const int offs = kb * 8 + 2 * tig;
            uint2 x00 = *(const uint2*)(Arow + offs);
            uint2 x01 = *(const uint2*)(Arow + 8 * APAD + offs);
            uint2 x10 = *(const uint2*)(Arow + 16 * APAD + offs);
            uint2 x11 = *(const uint2*)(Arow + 24 * APAD + offs);
            uint32_t a0[4] = { x00.x, x01.x, x00.y, x01.y };
            uint32_t a1[4] = { x10.x, x11.x, x10.y, x11.y };
            const float4* bp = (const float4*)(Bbase + kb * 32 * 20);
            float4 bv0 = bp[0], bv1 = bp[1], bv2 = bp[2], bv3 = bp[3];
            mma_tf32(acc[0][0], a0, __float_as_uint(bv0.x), __float_as_uint(bv0.y));
            mma_tf32(acc[1][0], a1, __float_as_uint(bv0.x), __float_as_uint(bv0.y));
            mma_tf32(acc[0][1], a0, __float_as_uint(bv0.z), __float_as_uint(bv0.w));
            mma_tf32(acc[1][1], a1, __float_as_uint(bv0.z), __float_as_uint(bv0.w));
            mma_tf32(acc[0][2], a0, __float_as_uint(bv1.x), __float_as_uint(bv1.y));
            mma_tf32(acc[1][2], a1, __float_as_uint(bv1.x), __float_as_uint(bv1.y));
            mma_tf32(acc[0][3], a0, __float_as_uint(bv1.z), __float_as_uint(bv1.w));
            mma_tf32(acc[1][3], a1, __float_as_uint(bv1.z), __float_as_uint(bv1.w));
            mma_tf32(acc[0][4], a0, __float_as_uint(bv2.x), __float_as_uint(bv2.y));
            mma_tf32(acc[1][4], a1, __float_as_uint(bv2.x), __float_as_uint(bv2.y));
            mma_tf32(acc[0][5], a0, __float_as_uint(bv2.z), __float_as_uint(bv2.w));
            mma_tf32(acc[1][5], a1, __float_as_uint(bv2.z), __float_as_uint(bv2.w));
            mma_tf32(acc[0][6], a0, __float_as_uint(bv3.x), __float_as_uint(bv3.y));
            mma_tf32(acc[1][6], a1, __float_as_uint(bv3.x), __float_as_uint(bv3.y));
            mma_tf32(acc[0][7], a0, __float_as_uint(bv3.z), __float_as_uint(bv3.w));
            mma_tf32(acc[1][7], a1, __float_as_uint(bv3.z), __float_as_uint(bv3.w));
        }
        // no tail barrier: next STS targets the other stage
    }

    // ---- epilogue: gate exchange via shfl, LSTM update; h stored tf32 ----
#pragma unroll
    for (int mt = 0; mt < 2; mt++) {
#pragma unroll
        for (int row = 0; row < 2; row++) {
            int m = wm * 32 + mt * 16 + row * 8 + g;
            int py = m >> 4, px = m & 15;
            int yy = y0 + py, xx = x0 + px;
            bool valid = (yy < Ho) && (xx < Wo);
            int ob = b * hb + (yy * Wo + xx) * 32;
#pragma unroll
            for (int nt = 0; nt < 8; nt++) {
                float za = acc[mt][nt][row * 2 + 0];
                float zb = acc[mt][nt][row * 2 + 1];
                float xc = __shfl_xor_sync(0xffffffffu, za, 1);
                float xo = __shfl_xor_sync(0xffffffffu, zb, 1);
                if (!(tig & 1) && valid) {
                    int f = wn * 16 + nt * 2 + (tig >> 1);
                    float zi = za + bias[f];
                    float zf = zb + bias[32 + f];
                    float zc = xc + bias[64 + f];
                    float zo = xo + bias[96 + f];
                    float cold = cbuf[ob + f];
                    float cn = fmaf(hsig(zf), cold, hsig(zi) * fmaxf(zc, 0.0f));
                    cbuf[ob + f] = cn;
                    hout[ob + f] = tf32r(hsig(zo) * fmaxf(cn, 0.0f));
                }
            }
        }
    }
}

// Fused maxpool + dense1 partials; 4 batches per block to cut Wd1 re-reads 4x.
// Grid (NCHUNK, 4): block handles chunk ch for batches 4*bg .. 4*bg+3.
__global__ void __launch_bounds__(128) pooldense_kernel(
    const float* __restrict__ h2, const float* __restrict__ Wd1, float* __restrict__ part)
{
    int ch = blockIdx.x, bg = blockIdx.y;
    int start = ch * CHUNK;
    float s[4][10];
#pragma unroll
    for (int q = 0; q < 4; q++)
#pragma unroll
        for (int j = 0; j < 10; j++) s[q][j] = 0.0f;

    for (int i = start + threadIdx.x; i < start + CHUNK; i += 128) {
        int c = i & 31; int t2 = i >> 5;
        int pw = t2 % 22; t2 /= 22;
        int ph = t2 % 23;
        int t = t2 / 23;
        const float* w = Wd1 + (long)i * 10;
        float wv[10];
#pragma unroll
        for (int j = 0; j < 10; j++) wv[j] = w[j];
#pragma unroll
        for (int q = 0; q < 4; q++) {
            int b = bg * 4 + q;
            const float* base = h2 + (((t * BB + b) * HO2 + 2 * ph) * WO2 + 2 * pw) * 32 + c;
            float v = fmaxf(fmaxf(base[0], base[32]),
                            fmaxf(base[WO2 * 32], base[WO2 * 32 + 32]));
#pragma unroll
            for (int j = 0; j < 10; j++) s[q][j] = fmaf(v, wv[j], s[q][j]);
        }
    }
    __shared__ float red[40][128];
#pragma unroll
    for (int q = 0; q < 4; q++)
#pragma unroll
        for (int j = 0; j < 10; j++) red[q * 10 + j][threadIdx.x] = s[q][j];
    __syncthreads();
    for (int off = 64; off > 0; off >>= 1) {
        if (threadIdx.x < off) {
#pragma unroll
            for (int r = 0; r < 40; r++)
                red[r][threadIdx.x] += red[r][threadIdx.x + off];
        }
        __syncthreads();
    }
    if (threadIdx.x < 40) {
        int q = threadIdx.x / 10, j = threadIdx.x % 10;
        int b = bg * 4 + q;
        part[(ch * BB + b) * 10 + j] = red[threadIdx.x][0];
    }
}

__global__ void final_kernel(const float* __restrict__ part,
                             const float* __restrict__ bd1,
                             const float* __restrict__ Wd2,
                             const float* __restrict__ bd2,
                             float* __restrict__ out)
{
    __shared__ float sd1[BB][10];
    int tid = threadIdx.x;
    if (tid < BB * 10) {
        int b = tid / 10, j = tid % 10;
        float s = bd1[j];
        for (int ch = 0; ch < NCHUNK; ch++)
            s += part[(ch * BB + b) * 10 + j];
        sd1[b][j] = s;
    }
    __syncthreads();
    if (tid < BB) {
        float o = bd2[0];
#pragma unroll
        for (int j = 0; j < 10; j++)
            o = fmaf(sd1[tid][j], Wd2[j], o);
        out[tid] = o;
    }
}

// ---------------- launcher ----------------
extern "C" void kernel_launch(void* const* d_in, const int* in_sizes, int n_in,
                              void* d_out, int out_size) {
    const float* x   = (const float*)d_in[0];
    const float* W1p = (const float*)d_in[1];
    const float* U1p = (const float*)d_in[2];
    const float* b1p = (const float*)d_in[3];
    const float* W2p = (const float*)d_in[4];
    const float* U2p = (const float*)d_in[5];
    const float* b2p = (const float*)d_in[6];
    const float* Wd1 = (const float*)d_in[7];
    const float* bd1 = (const float*)d_in[8];
    const float* Wd2 = (const float*)d_in[9];
    const float* bd2 = (const float*)d_in[10];
    float* out = (float*)d_out;

    float *h1, *h2, *cb, *hz, *part, *B1, *B2, *xr;
    cudaGetSymbolAddress((void**)&h1, g_h1);
    cudaGetSymbolAddress((void**)&h2, g_h2);
    cudaGetSymbolAddress((void**)&cb, g_c);
    cudaGetSymbolAddress((void**)&hz, g_hzero);
    cudaGetSymbolAddress((void**)&part, g_part);
    cudaGetSymbolAddress((void**)&B1, g_B1);
    cudaGetSymbolAddress((void**)&B2, g_B2);
    cudaGetSymbolAddress((void**)&xr, g_xr);

    static bool attr_done = false;
    if (!attr_done) {
        cudaFuncSetAttribute(fused_step_kernel,
                             cudaFuncAttributeMaxDynamicSharedMemorySize, SMEM_BYTES);
        attr_done = true;
    }

    const int nprep = 7 * 4096 + 12 * 4096 + BB * TT * H1 * W1 * C1;
    prep_kernel<<<(nprep + 255) / 256, 256>>>(W1p, U1p, W2p, U2p, x, B1, B2, xr);
    cudaMemsetAsync(cb, 0, sizeof(float) * 2 * BB * HO1 * WO1 * FF, 0);
    float* cb2 = cb + BB * HO1 * WO1 * FF;

    dim3 g(3, 6, 32);
    for (int t = 0; t <= TT; t++) {
        fused_step_kernel<<<g, 256, SMEM_BYTES>>>(t, xr, h1, h2, hz, cb, cb2,
                                                  B1, B2, b1p, b2p);
    }

    pooldense_kernel<<<dim3(NCHUNK, 4), 128>>>(h2, Wd1, part);
    final_kernel<<<1, 256>>>(part, bd1, Wd2, bd2, out);
}

// round 15
// speedup vs baseline: 1.3660x; 1.3660x over previous
#include <cuda_runtime.h>
#include <cuda_fp16.h>
#include <cstdint>

// ---------------- problem constants ----------------
#define BB 16
#define TT 12
#define FF 32
#define H1 48
#define W1 48
#define C1 3
#define HO1 47
#define WO1 46
#define H2 47
#define W2 46
#define HO2 46
#define WO2 44
#define NCHUNK 256
#define CHUNK 759   // 256*759 = 194304 exactly

#define H1SLICE (BB * HO1 * WO1 * FF)
#define H2SLICE (BB * HO2 * WO2 * FF)

// ---------------- device scratch ----------------
__device__ __half g_h1[(long)TT * BB * HO1 * WO1 * FF];
__device__ __half g_h2[(long)TT * BB * HO2 * WO2 * FF];
__device__ float  g_c[2 * BB * HO1 * WO1 * FF];
__device__ __half g_hzero[BB * HO1 * WO1 * FF];         // zero-init, never written
__device__ float  g_part[NCHUNK * BB * 10];
__device__ __half g_xr[BB * TT * H1 * W1 * C1];         // fp16 input
// B chunk tiles in fp16 fragment layout:
// half index within chunk: [wn(1b)|ks(1b)|lane(5b)|w=nt*2+r(4b)|e(1b)] (4096 halves)
__device__ __half g_B1[7 * 4096];
__device__ __half g_B2[12 * 4096];

__device__ __forceinline__ float hsig(float x) {
    return fminf(fmaxf(fmaf(0.2f, x, 0.5f), 0.0f), 1.0f);
}
// m16n8k16 fp16 MMA, fp32 accumulate: D += A*B
__device__ __forceinline__ void mma_f16(float* d, const uint32_t* a, uint32_t b0, uint32_t b1) {
    asm volatile(
        "mma.sync.aligned.m16n8k16.row.col.f32.f16.f16.f32 "
        "{%0,%1,%2,%3}, {%4,%5,%6,%7}, {%8,%9}, {%0,%1,%2,%3};"
        : "+f"(d[0]), "+f"(d[1]), "+f"(d[2]), "+f"(d[3])
        : "r"(a[0]), "r"(a[1]), "r"(a[2]), "r"(a[3]), "r"(b0), "r"(b1));
}
__device__ __forceinline__ uint32_t pack_h2(__half lo, __half hi) {
    __half2 h = __halves2half2(lo, hi);
    return *reinterpret_cast<uint32_t*>(&h);
}

// Build fp16 B chunk tiles in fragment layout + fp16 x.
// L1: chunk0 = packed x (k = tap*3+ci, 18 used), chunks 1..6 = h taps.
// L2: chunks 0..5 = x taps, 6..11 = h taps.  n = 4f+gate -> col = (n&3)*32 + (n>>2).
__global__ void prep_kernel(const float* __restrict__ W1p, const float* __restrict__ U1p,
                            const float* __restrict__ W2p, const float* __restrict__ U2p,
                            const float* __restrict__ x,
                            __half* __restrict__ B1, __half* __restrict__ B2,
                            __half* __restrict__ xr)
{
    int idx = blockIdx.x * blockDim.x + threadIdx.x;
    const int t1 = 7 * 4096, t2 = t1 + 12 * 4096;
    const int nx = BB * TT * H1 * W1 * C1;
    if (idx < t2) {
        int isL1 = idx < t1;
        int local = isL1 ? idx : idx - t1;
        int c = local >> 12, r = local & 4095;
        int e = r & 1;
        int w = (r >> 1) & 15;
        int lane = (r >> 5) & 31;
        int ks = (r >> 10) & 1;
        int wn = r >> 11;
        int nt = w >> 1, rr = w & 1;
        int n = wn * 64 + nt * 8 + (lane >> 2);
        int k = ks * 16 + 2 * (lane & 3) + 8 * rr + e;
        int col = (n & 3) * 32 + (n >> 2);
        float v;
        if (isL1) {
            if (c == 0) v = (k < 18) ? W1p[k * 128 + col] : 0.0f;
            else        v = U1p[((c - 1) * 32 + k) * 128 + col];
            B1[local] = __float2half_rn(v);
        } else {
            v = (c < 6) ? W2p[(c * 32 + k) * 128 + col]
                        : U2p[((c - 6) * 32 + k) * 128 + col];
            B2[local] = __float2half_rn(v);
        }
    } else if (idx < t2 + nx) {
        int i = idx - t2;
        xr[i] = __float2half_rn(x[i]);
    }
}

// Fused step F(t): layer1 step t + layer2 step t-1, fp16 m16n8k16 implicit GEMM.
// Register prefetch, single smem stage (R13 skeleton).
// Grid (3,6,32): z = layer*16+batch; 256 threads = 8 warps (wm=warp&3, wn=warp>>2).
__global__ void __launch_bounds__(256, 2) fused_step_kernel(
    int t,
    const __half* __restrict__ xr,
    __half* __restrict__ h1, __half* __restrict__ h2,
    const __half* __restrict__ hz,
    float* __restrict__ cb1, float* __restrict__ cb2,
    const __half* __restrict__ gB1, const __half* __restrict__ gB2,
    const float* __restrict__ b1, const float* __restrict__ b2)
{
    __shared__ uint32_t As[128 * 20];  // per row m: [ks0 perm 8 u32][ks1 perm 8][pad 4]
    __shared__ uint32_t Bs[128 * 20];  // per entry (wn,ks,lane): 16 u32 frag + pad 4

    const int tid = threadIdx.x;
    const int lane = tid & 31;
    const int warp = tid >> 5;
    const int g = lane >> 2, tig = lane & 3;
    const int wm = warp & 3, wn = warp >> 2;
    const int z = blockIdx.z;
    const int layer = z >> 4, b = z & 15;
    const int y0 = blockIdx.y * 8, x0 = blockIdx.x * 16;

    if (layer == 0 && t >= TT) return;
    if (layer == 1 && t == 0) return;
    const int s = layer ? (t - 1) : t;

    const int Ho = layer ? HO2 : HO1;
    const int Wo = layer ? WO2 : WO1;
    const int hb = Ho * Wo * 32;
    const long slice = layer ? (long)H2SLICE : (long)H1SLICE;
    const __half* gB = layer ? gB2 : gB1;
    const float* bias = layer ? b2 : b1;
    float* cbuf = layer ? cb2 : cb1;
    __half* hseq = layer ? h2 : h1;
    __half* hout = hseq + s * slice;
    const int have_h = (s != 0);
    const __half* hprev = (have_h ? (hseq + (s - 1) * slice) : hz) + b * hb;
    const __half* xsrc2 = h1 + (long)s * H1SLICE + b * (HO1 * WO1 * 32);

    const int nch = layer ? (have_h ? 12 : 6) : (have_h ? 7 : 1);

    float acc[2][8][4];
#pragma unroll
    for (int mt = 0; mt < 2; mt++)
#pragma unroll
        for (int nt = 0; nt < 8; nt++)
#pragma unroll
            for (int j = 0; j < 4; j++) acc[mt][nt][j] = 0.0f;

    const int sm_m = tid >> 1, sm_kh = tid & 1;     // A: row m, k-half
    const int sm_py = sm_m >> 4, sm_px = sm_m & 15;
    const int be = tid >> 1, bhb = tid & 1;         // B: entry, half-block

    uint4 qA0, qA1;   // A prefetch (raw k order: pairs k0..k15 of this k-half)
    uint4 qB0, qB1;   // B prefetch (fragment order)

    auto ldgB = [&](int c) {
        const uint4* sp = (const uint4*)(gB + (c << 12)) + be * 4 + bhb * 2;
        qB0 = sp[0]; qB1 = sp[1];
    };
    auto ldgA = [&](int c) {
        if (layer == 0 && c == 0) {
            const __half* xb = xr + (long)(b * TT + s) * (48 * 48 * 3);
            __half tmp[16];
#pragma unroll
            for (int i = 0; i < 16; i++) {
                int k = sm_kh * 16 + i;
                __half v = __float2half_rn(0.0f);
                if (k < 18) {
                    int tap = k / 3, ci = k - tap * 3;
                    int dy = tap / 3, dx = tap - dy * 3;
                    int gy = y0 + sm_py + dy, gx = x0 + sm_px + dx;
                    if (gy < 48 && gx < 48) v = xb[(gy * 48 + gx) * 3 + ci];
                }
                tmp[i] = v;
            }
            qA0 = make_uint4(pack_h2(tmp[0], tmp[1]), pack_h2(tmp[2], tmp[3]),
                             pack_h2(tmp[4], tmp[5]), pack_h2(tmp[6], tmp[7]));
            qA1 = make_uint4(pack_h2(tmp[8], tmp[9]), pack_h2(tmp[10], tmp[11]),
                             pack_h2(tmp[12], tmp[13]), pack_h2(tmp[14], tmp[15]));
        } else {
            int cc, isH;
            if (layer == 0) { cc = c - 1; isH = 1; }
            else { isH = (c >= 6); cc = isH ? (c - 6) : c; }
            int dy = cc / 3, dx = cc - dy * 3;
            const __half* src; int Hs, Ws, gx;
            int gy = y0 + sm_py + dy;
            if (isH) { src = hprev; Hs = Ho; Ws = Wo; gx = x0 + sm_px + dx - 1; }
            else     { src = xsrc2; Hs = H2; Ws = W2; gx = x0 + sm_px + dx; }
            bool ok = ((unsigned)gy < (unsigned)Hs) && ((unsigned)gx < (unsigned)Ws);
            if (ok) {
                const uint4* sp = (const uint4*)(src + (gy * Ws + gx) * 32 + sm_kh * 16);
                qA0 = sp[0]; qA1 = sp[1];
            } else {
                qA0 = qA1 = make_uint4(0u, 0u, 0u, 0u);
            }
        }
    };

    ldgA(0);
    ldgB(0);

    for (int c = 0; c < nch; c++) {
        // ---- STS prefetched chunk (A permuted: p = u0,u4,u1,u5,u2,u6,u3,u7) ----
        {
            uint4* dB = (uint4*)(Bs + be * 20 + bhb * 8);
            dB[0] = qB0; dB[1] = qB1;
            uint4* dA = (uint4*)(As + sm_m * 20 + sm_kh * 8);
            dA[0] = make_uint4(qA0.x, qA1.x, qA0.y, qA1.y);
            dA[1] = make_uint4(qA0.z, qA1.z, qA0.w, qA1.w);
        }
        __syncthreads();

        // ---- issue next chunk's LDGs (latency hidden by MMA phase) ----
        if (c + 1 < nch) { ldgA(c + 1); ldgB(c + 1); }

        // ---- MMA phase: 2 k16-steps ----
        const uint32_t* Arow = As + (wm * 32 + g) * 20;
#pragma unroll
        for (int ks = 0; ks < 2; ks++) {
            const int offs = ks * 8 + tig * 2;
            uint2 x00 = *(const uint2*)(Arow + offs);            // mt0 row g   : (a0,a2)
            uint2 x01 = *(const uint2*)(Arow + 8 * 20 + offs);   // mt0 row g+8 : (a1,a3)
            uint2 x10 = *(const uint2*)(Arow + 16 * 20 + offs);  // mt1 row g
            uint2 x11 = *(const uint2*)(Arow + 24 * 20 + offs);  // mt1 row g+8
            uint32_t a0[4] = { x00.x, x01.x, x00.y, x01.y };
            uint32_t a1[4] = { x10.x, x11.x, x10.y, x11.y };
            const uint4* bp = (const uint4*)(Bs + ((wn * 2 + ks) * 32 + lane) * 20);
            uint4 bv0 = bp[0], bv1 = bp[1], bv2 = bp[2], bv3 = bp[3];
            mma_f16(acc[0][0], a0, bv0.x, bv0.y);
            mma_f16(acc[1][0], a1, bv0.x, bv0.y);
            mma_f16(acc[0][1], a0, bv0.z, bv0.w);
            mma_f16(acc[1][1], a1, bv0.z, bv0.w);
            mma_f16(acc[0][2], a0, bv1.x, bv1.y);
            mma_f16(acc[1][2], a1, bv1.x, bv1.y);
            mma_f16(acc[0][3], a0, bv1.z, bv1.w);
            mma_f16(acc[1][3], a1, bv1.z, bv1.w);
            mma_f16(acc[0][4], a0, bv2.x, bv2.y);
            mma_f16(acc[1][4], a1, bv2.x, bv2.y);
            mma_f16(acc[0][5], a0, bv2.z, bv2.w);
            mma_f16(acc[1][5], a1, bv2.z, bv2.w);
            mma_f16(acc[0][6], a0, bv3.x, bv3.y);
            mma_f16(acc[1][6], a1, bv3.x, bv3.y);
            mma_f16(acc[0][7], a0, bv3.z, bv3.w);
            mma_f16(acc[1][7], a1, bv3.z, bv3.w);
        }
        __syncthreads();
    }

    // ---- epilogue: gate exchange via shfl, LSTM update; h stored fp16 ----
#pragma unroll
    for (int mt = 0; mt < 2; mt++) {
#pragma unroll
        for (int row = 0; row < 2; row++) {
            int m = wm * 32 + mt * 16 + row * 8 + g;
            int py = m >> 4, px = m & 15;
            int yy = y0 + py, xx = x0 + px;
            bool valid = (yy < Ho) && (xx < Wo);
            int ob = b * hb + (yy * Wo + xx) * 32;
#pragma unroll
            for (int nt = 0; nt < 8; nt++) {
                float za = acc[mt][nt][row * 2 + 0];
                float zb = acc[mt][nt][row * 2 + 1];
                float xc = __shfl_xor_sync(0xffffffffu, za, 1);
                float xo = __shfl_xor_sync(0xffffffffu, zb, 1);
                if (!(tig & 1) && valid) {
                    int f = wn * 16 + nt * 2 + (tig >> 1);
                    float zi = za + bias[f];
                    float zf = zb + bias[32 + f];
                    float zc = xc + bias[64 + f];
                    float zo = xo + bias[96 + f];
                    float cold = cbuf[ob + f];
                    float cn = fmaf(hsig(zf), cold, hsig(zi) * fmaxf(zc, 0.0f));
                    cbuf[ob + f] = cn;
                    hout[ob + f] = __float2half_rn(hsig(zo) * fmaxf(cn, 0.0f));
                }
            }
        }
    }
}

// Fused maxpool + dense1 partials; 4 batches per block (Wd1 traffic 4x down).
__global__ void __launch_bounds__(128) pooldense_kernel(
    const __half* __restrict__ h2, const float* __restrict__ Wd1, float* __restrict__ part)
{
    int ch = blockIdx.x, bg = blockIdx.y;
    int start = ch * CHUNK;
    float s[4][10];
#pragma unroll
    for (int q = 0; q < 4; q++)
#pragma unroll
        for (int j = 0; j < 10; j++) s[q][j] = 0.0f;

    for (int i = start + threadIdx.x; i < start + CHUNK; i += 128) {
        int c = i & 31; int t2 = i >> 5;
        int pw = t2 % 22; t2 /= 22;
        int ph = t2 % 23;
        int t = t2 / 23;
        const float* w = Wd1 + (long)i * 10;
        float wv[10];
#pragma unroll
        for (int j = 0; j < 10; j++) wv[j] = w[j];
#pragma unroll
        for (int q = 0; q < 4; q++) {
            int b = bg * 4 + q;
            const __half* base = h2 + (((t * BB + b) * HO2 + 2 * ph) * WO2 + 2 * pw) * 32 + c;
            float v = fmaxf(fmaxf(__half2float(base[0]), __half2float(base[32])),
                            fmaxf(__half2float(base[WO2 * 32]),
                                  __half2float(base[WO2 * 32 + 32])));
#pragma unroll
            for (int j = 0; j < 10; j++) s[q][j] = fmaf(v, wv[j], s[q][j]);
        }
    }
    __shared__ float red[40][128];
#pragma unroll
    for (int q = 0; q < 4; q++)
#pragma unroll
        for (int j = 0; j < 10; j++) red[q * 10 + j][threadIdx.x] = s[q][j];
    __syncthreads();
    for (int off = 64; off > 0; off >>= 1) {
        if (threadIdx.x < off) {
#pragma unroll
            for (int r = 0; r < 40; r++)
                red[r][threadIdx.x] += red[r][threadIdx.x + off];
        }
        __syncthreads();
    }
    if (threadIdx.x < 40) {
        int q = threadIdx.x / 10, j = threadIdx.x % 10;
        int b = bg * 4 + q;
        part[(ch * BB + b) * 10 + j] = red[threadIdx.x][0];
    }
}

__global__ void final_kernel(const float* __restrict__ part,
                             const float* __restrict__ bd1,
                             const float* __restrict__ Wd2,
                             const float* __restrict__ bd2,
                             float* __restrict__ out)
{
    __shared__ float sd1[BB][10];
    int tid = threadIdx.x;
    if (tid < BB * 10) {
        int b = tid / 10, j = tid % 10;
        float s = bd1[j];
        for (int ch = 0; ch < NCHUNK; ch++)
            s += part[(ch * BB + b) * 10 + j];
        sd1[b][j] = s;
    }
    __syncthreads();
    if (tid < BB) {
        float o = bd2[0];
#pragma unroll
        for (int j = 0; j < 10; j++)
            o = fmaf(sd1[tid][j], Wd2[j], o);
        out[tid] = o;
    }
}

// ---------------- launcher ----------------
extern "C" void kernel_launch(void* const* d_in, const int* in_sizes, int n_in,
                              void* d_out, int out_size) {
    const float* x   = (const float*)d_in[0];
    const float* W1p = (const float*)d_in[1];
    const float* U1p = (const float*)d_in[2];
    const float* b1p = (const float*)d_in[3];
    const float* W2p = (const float*)d_in[4];
    const float* U2p = (const float*)d_in[5];
    const float* b2p = (const float*)d_in[6];
    const float* Wd1 = (const float*)d_in[7];
    const float* bd1 = (const float*)d_in[8];
    const float* Wd2 = (const float*)d_in[9];
    const float* bd2 = (const float*)d_in[10];
    float* out = (float*)d_out;

    __half *h1, *h2, *hz, *B1, *B2, *xr;
    float *cb, *part;
    cudaGetSymbolAddress((void**)&h1, g_h1);
    cudaGetSymbolAddress((void**)&h2, g_h2);
    cudaGetSymbolAddress((void**)&cb, g_c);
    cudaGetSymbolAddress((void**)&hz, g_hzero);
    cudaGetSymbolAddress((void**)&part, g_part);
    cudaGetSymbolAddress((void**)&B1, g_B1);
    cudaGetSymbolAddress((void**)&B2, g_B2);
    cudaGetSymbolAddress((void**)&xr, g_xr);

    const int nprep = 7 * 4096 + 12 * 4096 + BB * TT * H1 * W1 * C1;
    prep_kernel<<<(nprep + 255) / 256, 256>>>(W1p, U1p, W2p, U2p, x, B1, B2, xr);
    cudaMemsetAsync(cb, 0, sizeof(float) * 2 * BB * HO1 * WO1 * FF, 0);
    float* cb2 = cb + BB * HO1 * WO1 * FF;

    dim3 g(3, 6, 32);
    for (int t = 0; t <= TT; t++) {
        fused_step_kernel<<<g, 256>>>(t, xr, h1, h2, hz, cb, cb2,
                                      B1, B2, b1p, b2p);
    }

    pooldense_kernel<<<dim3(NCHUNK, 4), 128>>>(h2, Wd1, part);
    final_kernel<<<1, 256>>>(part, bd1, Wd2, bd2, out);
}

// round 17
// speedup vs baseline: 1.4247x; 1.0430x over previous
#include <cuda_runtime.h>
#include <cuda_fp16.h>
#include <cstdint>

// ---------------- problem constants ----------------
#define BB 16
#define TT 12
#define FF 32
#define H1 48
#define W1 48
#define C1 3
#define HO1 47
#define WO1 46
#define H2 47
#define W2 46
#define HO2 46
#define WO2 44
#define NCHUNK 256
#define CHUNK 759   // 256*759 = 194304 exactly

#define H1SLICE (BB * HO1 * WO1 * FF)
#define H2SLICE (BB * HO2 * WO2 * FF)

#define DEPTH 4
#define STG_U32 5120                       // per stage: As 2560 u32 + Bs 2560 u32
#define SMEM_BYTES (DEPTH * STG_U32 * 4)   // 80 KB

// channel permutation LUT (memory pair = Pinv8[logical pair]), nibble-packed
#define PINV8 0x75316420u

// ---------------- device scratch ----------------
// h stored fp16 with channel pairs permuted within each 16-channel half:
// logical channel f -> memory pos (f&16) | 2*Pinv8[(f>>1)&7] | (f&1)
__device__ __half g_h1[(long)TT * BB * HO1 * WO1 * FF];
__device__ __half g_h2[(long)TT * BB * HO2 * WO2 * FF];
__device__ float  g_c[2 * BB * HO1 * WO1 * FF];
__device__ __half g_hzero[BB * HO1 * WO1 * FF];         // zero-init, never written
__device__ float  g_part[NCHUNK * BB * 10];
__device__ __half g_xr[BB * TT * H1 * W1 * C1];         // fp16 input (raw order)
// B chunk tiles in fp16 fragment layout (same as R15)
__device__ __half g_B1[7 * 4096];
__device__ __half g_B2[12 * 4096];

__device__ __forceinline__ float hsig(float x) {
    return fminf(fmaxf(fmaf(0.2f, x, 0.5f), 0.0f), 1.0f);
}
__device__ __forceinline__ void mma_f16(float* d, const uint32_t* a, uint32_t b0, uint32_t b1) {
    asm volatile(
        "mma.sync.aligned.m16n8k16.row.col.f32.f16.f16.f32 "
        "{%0,%1,%2,%3}, {%4,%5,%6,%7}, {%8,%9}, {%0,%1,%2,%3};"
        : "+f"(d[0]), "+f"(d[1]), "+f"(d[2]), "+f"(d[3])
        : "r"(a[0]), "r"(a[1]), "r"(a[2]), "r"(a[3]), "r"(b0), "r"(b1));
}
__device__ __forceinline__ uint32_t pack_h2(__half lo, __half hi) {
    __half2 h = __halves2half2(lo, hi);
    return *reinterpret_cast<uint32_t*>(&h);
}
__device__ __forceinline__ uint32_t smem_u32(const void* p) {
    uint32_t a;
    asm("{ .reg .u64 t; cvta.to.shared.u64 t, %1; cvt.u32.u64 %0, t; }" : "=r"(a) : "l"(p));
    return a;
}
__device__ __forceinline__ void cp16(uint32_t d, const void* s, int sz) {
    asm volatile("cp.async.ca.shared.global [%0], [%1], 16, %2;"
                 :: "r"(d), "l"(s), "r"(sz) : "memory");
}
__device__ __forceinline__ void cp_commit() {
    asm volatile("cp.async.commit_group;" ::: "memory");
}
template <int N>
__device__ __forceinline__ void cp_wait() {
    asm volatile("cp.async.wait_group %0;" :: "n"(N) : "memory");
}
__device__ __forceinline__ int chperm(int f) {
    return (f & 16) | (((PINV8 >> (((f >> 1) & 7) * 4)) & 7) << 1) | (f & 1);
}

// Build fp16 B chunk tiles in fragment layout + fp16 x. (identical to R15)
__global__ void prep_kernel(const float* __restrict__ W1p, const float* __restrict__ U1p,
                            const float* __restrict__ W2p, const float* __restrict__ U2p,
                            const float* __restrict__ x,
                            __half* __restrict__ B1, __half* __restrict__ B2,
                            __half* __restrict__ xr)
{
    int idx = blockIdx.x * blockDim.x + threadIdx.x;
    const int t1 = 7 * 4096, t2 = t1 + 12 * 4096;
    const int nx = BB * TT * H1 * W1 * C1;
    if (idx < t2) {
        int isL1 = idx < t1;
        int local = isL1 ? idx : idx - t1;
        int c = local >> 12, r = local & 4095;
        int e = r & 1;
        int w = (r >> 1) & 15;
        int lane = (r >> 5) & 31;
        int ks = (r >> 10) & 1;
        int wn = r >> 11;
        int nt = w >> 1, rr = w & 1;
        int n = wn * 64 + nt * 8 + (lane >> 2);
        int k = ks * 16 + 2 * (lane & 3) + 8 * rr + e;
        int col = (n & 3) * 32 + (n >> 2);
        float v;
        if (isL1) {
            if (c == 0) v = (k < 18) ? W1p[k * 128 + col] : 0.0f;
            else        v = U1p[((c - 1) * 32 + k) * 128 + col];
            B1[local] = __float2half_rn(v);
        } else {
            v = (c < 6) ? W2p[(c * 32 + k) * 128 + col]
                        : U2p[((c - 6) * 32 + k) * 128 + col];
            B2[local] = __float2half_rn(v);
        }
    } else if (idx < t2 + nx) {
        int i = idx - t2;
        xr[i] = __float2half_rn(x[i]);
    }
}

// Fused step F(t): fp16 m16n8k16 implicit GEMM, cp.async 4-stage ring,
// h stored channel-permuted so A staging is a raw 32B copy.
// Grid (3,6,32): z = layer*16+batch; 256 threads = 8 warps (wm=warp&3, wn=warp>>2).
__global__ void __launch_bounds__(256, 2) fused_step_kernel(
    int t,
    const __half* __restrict__ xr,
    __half* __restrict__ h1, __half* __restrict__ h2,
    const __half* __restrict__ hz,
    float* __restrict__ cb1, float* __restrict__ cb2,
    const __half* __restrict__ gB1, const __half* __restrict__ gB2,
    const float* __restrict__ b1, const float* __restrict__ b2)
{
    extern __shared__ uint32_t sm[];   // DEPTH stages: [As 128*20 u32 | Bs 128*20 u32]

    const int tid = threadIdx.x;
    const int lane = tid & 31;
    const int warp = tid >> 5;
    const int g = lane >> 2, tig = lane & 3;
    const int wm = warp & 3, wn = warp >> 2;
    const int z = blockIdx.z;
    const int layer = z >> 4, b = z & 15;
    const int y0 = blockIdx.y * 8, x0 = blockIdx.x * 16;

    if (layer == 0 && t >= TT) return;
    if (layer == 1 && t == 0) return;
    const int s = layer ? (t - 1) : t;

    const int Ho = layer ? HO2 : HO1;
    const int Wo = layer ? WO2 : WO1;
    const int hb = Ho * Wo * 32;
    const long slice = layer ? (long)H2SLICE : (long)H1SLICE;
    const __half* gB = layer ? gB2 : gB1;
    const float* bias = layer ? b2 : b1;
    float* cbuf = layer ? cb2 : cb1;
    __half* hseq = layer ? h2 : h1;
    __half* hout = hseq + s * slice;
    const int have_h = (s != 0);
    const __half* hprev = (have_h ? (hseq + (s - 1) * slice) : hz) + b * hb;
    const __half* xsrc2 = h1 + (long)s * H1SLICE + b * (HO1 * WO1 * 32);

    const int nch = layer ? (have_h ? 12 : 6) : (have_h ? 7 : 1);

    float acc[2][8][4];
#pragma unroll
    for (int mt = 0; mt < 2; mt++)
#pragma unroll
        for (int nt = 0; nt < 8; nt++)
#pragma unroll
            for (int j = 0; j < 4; j++) acc[mt][nt][j] = 0.0f;

    const int sm_m = tid >> 1, sm_kh = tid & 1;     // A: row m, k-half; B: entry, half
    const int sm_py = sm_m >> 4, sm_px = sm_m & 15;

    // issue chunk c's async copies into stage c&3 (+ one commit group)
    auto issue = [&](int c) {
        uint32_t* st = sm + (c & 3) * STG_U32;
        // B: raw fragment copy — entry (tid>>1), half (tid&1): 16 bytes each x2
        {
            const __half* sp = gB + (c << 12) + tid * 16;
            uint32_t dst = smem_u32(st + 2560 + sm_m * 20 + sm_kh * 8);
            cp16(dst, sp, 16);
            cp16(dst + 16, sp + 8, 16);
        }
        // A
        if (layer == 0 && c == 0) {
            // packed-x chunk: register gather + STS in fragment order
            const __half* xb = xr + (long)(b * TT + s) * (48 * 48 * 3);
            __half tmp[16];
#pragma unroll
            for (int i = 0; i < 16; i++) {
                int k = sm_kh * 16 + i;
                __half v = __float2half_rn(0.0f);
                if (k < 18) {
                    int tap = k / 3, ci = k - tap * 3;
                    int dy = tap / 3, dx = tap - dy * 3;
                    int gy = y0 + sm_py + dy, gx = x0 + sm_px + dx;
                    if (gy < 48 && gx < 48) v = xb[(gy * 48 + gx) * 3 + ci];
                }
                tmp[i] = v;
            }
            uint32_t u[8];
#pragma unroll
            for (int j = 0; j < 8; j++) u[j] = pack_h2(tmp[2 * j], tmp[2 * j + 1]);
            uint4* dA = (uint4*)(st + sm_m * 20 + sm_kh * 8);
            dA[0] = make_uint4(u[0], u[4], u[1], u[5]);
            dA[1] = make_uint4(u[2], u[6], u[3], u[7]);
        } else {
            // h/x chunk: raw 32B copy (source already channel-permuted)
            int cc, isH;
            if (layer == 0) { cc = c - 1; isH = 1; }
            else { isH = (c >= 6); cc = isH ? (c - 6) : c; }
            int dy = cc / 3, dx = cc - dy * 3;
            const __half* src; int Hs, Ws, gx;
            int gy = y0 + sm_py + dy;
            if (isH) { src = hprev; Hs = Ho; Ws = Wo; gx = x0 + sm_px + dx - 1; }
            else     { src = xsrc2; Hs = H2; Ws = W2; gx = x0 + sm_px + dx; }
            bool ok = ((unsigned)gy < (unsigned)Hs) && ((unsigned)gx < (unsigned)Ws);
            const __half* sp = src + (ok ? (gy * Ws + gx) * 32 : 0) + sm_kh * 16;
            int sz = ok ? 16 : 0;
            uint32_t dst = smem_u32(st + sm_m * 20 + sm_kh * 8);
            cp16(dst, sp, sz);
            cp16(dst + 16, sp + 8, sz);
        }
        cp_commit();
    };

    // prologue: up to 3 chunks in flight
    issue(0);
    if (nch > 1) issue(1);
    if (nch > 2) issue(2);

    for (int c = 0; c < nch; c++) {
        const int rem = nch - 1 - c;          // chunks issued beyond c
        if (rem >= 2) cp_wait<2>();
        else if (rem == 1) cp_wait<1>();
        else cp_wait<0>();
        __syncthreads();                      // all warps' chunk-c data resident;
                                              // all warps past MMA(c-1)
        if (c + 3 < nch) issue(c + 3);        // writes stage (c-1)&3 -- safe

        const uint32_t* st = sm + (c & 3) * STG_U32;
        const uint32_t* Arow = st + (wm * 32 + g) * 20;
        const uint32_t* Bst = st + 2560;
#pragma unroll
        for (int ks = 0; ks < 2; ks++) {
            const int offs = ks * 8 + tig * 2;
            uint2 x00 = *(const uint2*)(Arow + offs);
            uint2 x01 = *(const uint2*)(Arow + 8 * 20 + offs);
            uint2 x10 = *(const uint2*)(Arow + 16 * 20 + offs);
            uint2 x11 = *(const uint2*)(Arow + 24 * 20 + offs);
            uint32_t a0[4] = { x00.x, x01.x, x00.y, x01.y };
            uint32_t a1[4] = { x10.x, x11.x, x10.y, x11.y };
            const uint4* bp = (const uint4*)(Bst + ((wn * 2 + ks) * 32 + lane) * 20);
            uint4 bv0 = bp[0], bv1 = bp[1], bv2 = bp[2], bv3 = bp[3];
            mma_f16(acc[0][0], a0, bv0.x, bv0.y);
            mma_f16(acc[1][0], a1, bv0.x, bv0.y);
            mma_f16(acc[0][1], a0, bv0.z, bv0.w);
            mma_f16(acc[1][1], a1, bv0.z, bv0.w);
            mma_f16(acc[0][2], a0, bv1.x, bv1.y);
            mma_f16(acc[1][2], a1, bv1.x, bv1.y);
            mma_f16(acc[0][3], a0, bv1.z, bv1.w);
            mma_f16(acc[1][3], a1, bv1.z, bv1.w);
            mma_f16(acc[0][4], a0, bv2.x, bv2.y);
            mma_f16(acc[1][4], a1, bv2.x, bv2.y);
            mma_f16(acc[0][5], a0, bv2.z, bv2.w);
            mma_f16(acc[1][5], a1, bv2.z, bv2.w);
            mma_f16(acc[0][6], a0, bv3.x, bv3.y);
            mma_f16(acc[1][6], a1, bv3.x, bv3.y);
            mma_f16(acc[0][7], a0, bv3.z, bv3.w);
            mma_f16(acc[1][7], a1, bv3.z, bv3.w);
        }
    }

    // ---- epilogue: gate exchange via shfl, LSTM update; h stored fp16 PERMUTED ----
#pragma unroll
    for (int mt = 0; mt < 2; mt++) {
#pragma unroll
        for (int row = 0; row < 2; row++) {
            int m = wm * 32 + mt * 16 + row * 8 + g;
            int py = m >> 4, px = m & 15;
            int yy = y0 + py, xx = x0 + px;
            bool valid = (yy < Ho) && (xx < Wo);
            int ob = b * hb + (yy * Wo + xx) * 32;
#pragma unroll
            for (int nt = 0; nt < 8; nt++) {
                float za = acc[mt][nt][row * 2 + 0];
                float zb = acc[mt][nt][row * 2 + 1];
                float xc = __shfl_xor_sync(0xffffffffu, za, 1);
                float xo = __shfl_xor_sync(0xffffffffu, zb, 1);
                if (!(tig & 1) && valid) {
                    int f = wn * 16 + nt * 2 + (tig >> 1);
                    float zi = za + bias[f];
                    float zf = zb + bias[32 + f];
                    float zc = xc + bias[64 + f];
                    float zo = xo + bias[96 + f];
                    float cold = cbuf[ob + f];
                    float cn = fmaf(hsig(zf), cold, hsig(zi) * fmaxf(zc, 0.0f));
                    cbuf[ob + f] = cn;
                    hout[ob + chperm(f)] = __float2half_rn(hsig(zo) * fmaxf(cn, 0.0f));
                }
            }
        }
    }
}

// Fused maxpool + dense1 partials; 4 batches per block; h2 channels are permuted.
__global__ void __launch_bounds__(128) pooldense_kernel(
    const __half* __restrict__ h2, const float* __restrict__ Wd1, float* __restrict__ part)
{
    int ch = blockIdx.x, bg = blockIdx.y;
    int start = ch * CHUNK;
    float s[4][10];
#pragma unroll
    for (int q = 0; q < 4; q++)
#pragma unroll
        for (int j = 0; j < 10; j++) s[q][j] = 0.0f;

    for (int i = start + threadIdx.x; i < start + CHUNK; i += 128) {
        int c = i & 31; int t2 = i >> 5;
        int pw = t2 % 22; t2 /= 22;
        int ph = t2 % 23;
        int t = t2 / 23;
        int cm = chperm(c);
        const float* w = Wd1 + (long)i * 10;
        float wv[10];
#pragma unroll
        for (int j = 0; j < 10; j++) wv[j] = w[j];
#pragma unroll
        for (int q = 0; q < 4; q++) {
            int b = bg * 4 + q;
            const __half* base = h2 + (((t * BB + b) * HO2 + 2 * ph) * WO2 + 2 * pw) * 32 + cm;
            float v = fmaxf(fmaxf(__half2float(base[0]), __half2float(base[32])),
                            fmaxf(__half2float(base[WO2 * 32]),
                                  __half2float(base[WO2 * 32 + 32])));
#pragma unroll
            for (int j = 0; j < 10; j++) s[q][j] = fmaf(v, wv[j], s[q][j]);
        }
    }
    __shared__ float red[40][128];
#pragma unroll
    for (int q = 0; q < 4; q++)
#pragma unroll
        for (int j = 0; j < 10; j++) red[q * 10 + j][threadIdx.x] = s[q][j];
    __syncthreads();
    for (int off = 64; off > 0; off >>= 1) {
        if (threadIdx.x < off) {
#pragma unroll
            for (int r = 0; r < 40; r++)
                red[r][threadIdx.x] += red[r][threadIdx.x + off];
        }
        __syncthreads();
    }
    if (threadIdx.x < 40) {
        int q = threadIdx.x / 10, j = threadIdx.x % 10;
        int b = bg * 4 + q;
        part[(ch * BB + b) * 10 + j] = red[threadIdx.x][0];
    }
}

__global__ void final_kernel(const float* __restrict__ part,
                             const float* __restrict__ bd1,
                             const float* __restrict__ Wd2,
                             const float* __restrict__ bd2,
                             float* __restrict__ out)
{
    __shared__ float sd1[BB][10];
    int tid = threadIdx.x;
    if (tid < BB * 10) {
        int b = tid / 10, j = tid % 10;
        float s = bd1[j];
        for (int ch = 0; ch < NCHUNK; ch++)
            s += part[(ch * BB + b) * 10 + j];
        sd1[b][j] = s;
    }
    __syncthreads();
    if (tid < BB) {
        float o = bd2[0];
#pragma unroll
        for (int j = 0; j < 10; j++)
            o = fmaf(sd1[tid][j], Wd2[j], o);
        out[tid] = o;
    }
}

// ---------------- launcher ----------------
extern "C" void kernel_launch(void* const* d_in, const int* in_sizes, int n_in,
                              void* d_out, int out_size) {
    const float* x   = (const float*)d_in[0];
    const float* W1p = (const float*)d_in[1];
    const float* U1p = (const float*)d_in[2];
    const float* b1p = (const float*)d_in[3];
    const float* W2p = (const float*)d_in[4];
    const float* U2p = (const float*)d_in[5];
    const float* b2p = (const float*)d_in[6];
    const float* Wd1 = (const float*)d_in[7];
    const float* bd1 = (const float*)d_in[8];
    const float* Wd2 = (const float*)d_in[9];
    const float* bd2 = (const float*)d_in[10];
    float* out = (float*)d_out;

    __half *h1, *h2, *hz, *B1, *B2, *xr;
    float *cb, *part;
    cudaGetSymbolAddress((void**)&h1, g_h1);
    cudaGetSymbolAddress((void**)&h2, g_h2);
    cudaGetSymbolAddress((void**)&cb, g_c);
    cudaGetSymbolAddress((void**)&hz, g_hzero);
    cudaGetSymbolAddress((void**)&part, g_part);
    cudaGetSymbolAddress((void**)&B1, g_B1);
    cudaGetSymbolAddress((void**)&B2, g_B2);
    cudaGetSymbolAddress((void**)&xr, g_xr);

    cudaFuncSetAttribute(fused_step_kernel,
                         cudaFuncAttributeMaxDynamicSharedMemorySize, SMEM_BYTES);

    const int nprep = 7 * 4096 + 12 * 4096 + BB * TT * H1 * W1 * C1;
    prep_kernel<<<(nprep + 255) / 256, 256>>>(W1p, U1p, W2p, U2p, x, B1, B2, xr);
    cudaMemsetAsync(cb, 0, sizeof(float) * 2 * BB * HO1 * WO1 * FF, 0);
    float* cb2 = cb + BB * HO1 * WO1 * FF;

    dim3 g(3, 6, 32);
    for (int t = 0; t <= TT; t++) {
        fused_step_kernel<<<g, 256, SMEM_BYTES>>>(t, xr, h1, h2, hz, cb, cb2,
                                                  B1, B2, b1p, b2p);
    }

    pooldense_kernel<<<dim3(NCHUNK, 4), 128>>>(h2, Wd1, part);
    final_kernel<<<1, 256>>>(part, bd1, Wd2, bd2, out);
}